// round 16
// baseline (speedup 1.0000x reference)
#include <cuda_runtime.h>
#include <cuda_fp16.h>
#include <cstdint>
#include <math.h>

// ---------------- problem constants ----------------
#define BB     32
#define HH     56
#define WWI    56
#define DIMC   512
#define WSZ    7
#define SHF    3
#define NHEAD  16
#define HDIM   32
#define MLPD   2048
#define SQ     49
#define TOK    (BB*HH*WWI)   // 100352
#define WTOT   (BB*64)       // 2048

// weight-transpose offsets (elements) in the packed wT array
#define OW_QKV  0
#define OW_PROJ (512*1536)
#define OW_W1   (OW_PROJ + 512*512)
#define OW_W2   (OW_W1 + 512*2048)
#define WT_TOT  (OW_W2 + 2048*512)
#define BTAB_N  (4*16*64*64)
#define PREP_TOT (WT_TOT + BTAB_N)

// ---------------- scratch ----------------
__device__ __half g_wt  [WT_TOT];
__device__ __half g_win [(size_t)TOK*DIMC];
__device__ __half g_qkv [(size_t)TOK*3*DIMC];
__device__ __half g_att [(size_t)TOK*DIMC];
__device__ float  g_x1  [(size_t)TOK*DIMC];
__device__ __half g_ln2 [(size_t)TOK*DIMC];
__device__ __half g_m1  [(size_t)TOK*MLPD];
__device__ __half g_btab[BTAB_N];            // bias+mask table, 512 KB

__device__ __forceinline__ float gelu_f(float x) {
    return 0.5f * x * (1.0f + erff(x * 0.70710678118654752f));
}

// ---------------- PTX helpers ----------------
__device__ __forceinline__ uint32_t smem_u32(const void* p) {
    uint32_t a;
    asm("{ .reg .u64 t; cvta.to.shared.u64 t, %1; cvt.u32.u64 %0, t; }" : "=r"(a) : "l"(p));
    return a;
}
__device__ __forceinline__ void cpa16(uint32_t s, const void* g) {
    asm volatile("cp.async.cg.shared.global [%0], [%1], 16;" :: "r"(s), "l"(g));
}
__device__ __forceinline__ void cp_commit() {
    asm volatile("cp.async.commit_group;" ::: "memory");
}
__device__ __forceinline__ void ldx4(uint32_t* r, uint32_t a) {
    asm volatile("ldmatrix.sync.aligned.m8n8.x4.shared.b16 {%0,%1,%2,%3}, [%4];"
        : "=r"(r[0]), "=r"(r[1]), "=r"(r[2]), "=r"(r[3]) : "r"(a));
}
__device__ __forceinline__ void ldx4t(uint32_t* r, uint32_t a) {
    asm volatile("ldmatrix.sync.aligned.m8n8.x4.trans.shared.b16 {%0,%1,%2,%3}, [%4];"
        : "=r"(r[0]), "=r"(r[1]), "=r"(r[2]), "=r"(r[3]) : "r"(a));
}
__device__ __forceinline__ void ldx2(uint32_t* r, uint32_t a) {
    asm volatile("ldmatrix.sync.aligned.m8n8.x2.shared.b16 {%0,%1}, [%2];"
        : "=r"(r[0]), "=r"(r[1]) : "r"(a));
}
__device__ __forceinline__ void mma16816(float* d, const uint32_t* a, const uint32_t* b) {
    asm volatile("mma.sync.aligned.m16n8k16.row.col.f32.f16.f16.f32 "
        "{%0,%1,%2,%3}, {%4,%5,%6,%7}, {%8,%9}, {%0,%1,%2,%3};"
        : "+f"(d[0]), "+f"(d[1]), "+f"(d[2]), "+f"(d[3])
        : "r"(a[0]), "r"(a[1]), "r"(a[2]), "r"(a[3]), "r"(b[0]), "r"(b[1]));
}

// ---------------- fused prep: weight transpose + bias/mask table ---------
__global__ void prep_kernel(const float* __restrict__ Wqkv,
                            const float* __restrict__ Wproj,
                            const float* __restrict__ W1,
                            const float* __restrict__ W2,
                            const float* __restrict__ relb,
                            __half* __restrict__ T,
                            __half* __restrict__ BT)
{
    int i = blockIdx.x * 256 + threadIdx.x;
    if (i >= PREP_TOT) return;
    if (i < WT_TOT) {
        const float* W; int K, N, base;
        if (i < OW_PROJ)      { W = Wqkv;  K = 512;  N = 1536; base = OW_QKV; }
        else if (i < OW_W1)   { W = Wproj; K = 512;  N = 512;  base = OW_PROJ; }
        else if (i < OW_W2)   { W = W1;    K = 512;  N = 2048; base = OW_W1; }
        else                  { W = W2;    K = 2048; N = 512;  base = OW_W2; }
        int li = i - base;
        int n = li / K, k = li - n * K;
        T[i] = __float2half_rn(W[(size_t)k * N + n]);
    } else {
        int idx = i - WT_TOT;
        int j  = idx & 63;
        int ii = (idx >> 6) & 63;
        int h  = (idx >> 12) & 15;
        int wc = idx >> 16;
        float v;
        if (ii < SQ && j < SQ) {
            int yi = ii / 7, xi = ii - yi * 7;
            int yj = j / 7,  xj = j - yj * 7;
            v = relb[((yi - yj + 6) * 13 + (xi - xj + 6)) * NHEAD + h];
            int er = wc >> 1, ec = wc & 1;
            int mi = (er ? (yi < 4 ? 1 : 2) : 0) * 3 + (ec ? (xi < 4 ? 1 : 2) : 0);
            int mj = (er ? (yj < 4 ? 1 : 2) : 0) * 3 + (ec ? (xj < 4 ? 1 : 2) : 0);
            if (mi != mj) v -= 100.0f;
        } else {
            v = -20000.0f;
        }
        BT[idx] = __float2half_rn(v);
    }
}

// ---------------- LayerNorm (+ roll + window gather), fp16 out -----------
__global__ void ln_kernel(const float* __restrict__ src,
                          const float* __restrict__ gamma,
                          const float* __restrict__ beta,
                          __half* __restrict__ dst, int gather)
{
    int gw = (blockIdx.x * blockDim.x + threadIdx.x) >> 5;
    if (gw >= TOK) return;
    int lane = threadIdx.x & 31;

    int srow;
    if (gather) {
        int w  = gw / SQ, s = gw - w * SQ;
        int bb = w >> 6, nw = w & 63;
        int wy = nw >> 3, wx = nw & 7;
        int iy = s / WSZ, ix = s - iy * WSZ;
        int row = wy * WSZ + iy + SHF; if (row >= HH)  row -= HH;
        int col = wx * WSZ + ix + SHF; if (col >= WWI) col -= WWI;
        srow = (bb * HH + row) * WWI + col;
    } else {
        srow = gw;
    }

    const float4* sp = (const float4*)(src + (size_t)srow * DIMC);
    float4 v[4];
    float sum = 0.f, sq = 0.f;
#pragma unroll
    for (int i = 0; i < 4; i++) {
        v[i] = sp[lane + i * 32];
        sum += v[i].x + v[i].y + v[i].z + v[i].w;
        sq  += v[i].x*v[i].x + v[i].y*v[i].y + v[i].z*v[i].z + v[i].w*v[i].w;
    }
#pragma unroll
    for (int o = 16; o > 0; o >>= 1) {
        sum += __shfl_xor_sync(0xffffffffu, sum, o);
        sq  += __shfl_xor_sync(0xffffffffu, sq,  o);
    }
    float mean = sum * (1.0f / DIMC);
    float var  = sq  * (1.0f / DIMC) - mean * mean;
    float inv  = rsqrtf(var + 1e-5f);

    const float4* gp = (const float4*)gamma;
    const float4* bp = (const float4*)beta;
    size_t rb = (size_t)gw * DIMC;
#pragma unroll
    for (int i = 0; i < 4; i++) {
        float4 g = gp[lane + i * 32];
        float4 b = bp[lane + i * 32];
        __half2 h0, h1;
        h0.x = __float2half_rn((v[i].x - mean) * inv * g.x + b.x);
        h0.y = __float2half_rn((v[i].y - mean) * inv * g.y + b.y);
        h1.x = __float2half_rn((v[i].z - mean) * inv * g.z + b.z);
        h1.y = __float2half_rn((v[i].w - mean) * inv * g.w + b.w);
        int e = (lane + i * 32) * 4;
        uint2 pk;
        pk.x = *(uint32_t*)&h0;
        pk.y = *(uint32_t*)&h1;
        *(uint2*)(dst + rb + e) = pk;
    }
}

// ---------------- fp16 GEMM via mma.sync, 128x128x64, 2-stage (champion) -
// EPI 0: +bias, q-cols (cc<512) scaled -> fp16 outH      (QKV)
// EPI 1: +bias +add[map(row)] -> fp32 outF[map(row)]     (proj scatter)
// EPI 2: gelu(+bias) -> fp16 outH                        (MLP1)
// EPI 3: +bias +add[row*N] -> fp32 outF[row*N]           (MLP2)
#define GBM 128
#define GBN 128
#define GBK 64
#define STAGE  (32*1024)
#define OFF_A  0
#define OFF_B  16384
#define GEMM_SMEM (2*STAGE)

__device__ __forceinline__ void gemm_issue(
    uint32_t sb, const __half* A, const __half* B,
    int bm0, int bn0, int K, int k0, int stage, int tid)
{
    uint32_t stb = sb + stage * STAGE;
#pragma unroll
    for (int i = 0; i < 4; i++) {
        int idx = i * 256 + tid;
        int row = idx >> 3, cch = idx & 7;
        uint32_t soff = row * 128 + ((cch ^ (row & 7)) << 4);
        cpa16(stb + OFF_A + soff, A + (size_t)(bm0 + row) * K + k0 + cch * 8);
        cpa16(stb + OFF_B + soff, B + (size_t)(bn0 + row) * K + k0 + cch * 8);
    }
    cp_commit();
}

template<int EPI>
__global__ void __launch_bounds__(256, 2)
gemm_kernel(const __half* __restrict__ A, const __half* __restrict__ B,
            const float* __restrict__ bias, const float* __restrict__ add,
            float* __restrict__ outF, __half* __restrict__ outH,
            int N, int K)
{
    extern __shared__ char smc[];
    uint32_t sb = smem_u32(smc);
    int tid  = threadIdx.x;
    int lane = tid & 31;
    int warp = tid >> 5;
    int wm = warp & 1, wn = warp >> 1;
    int bm0 = blockIdx.y * GBM;
    int bn0 = blockIdx.x * GBN;
    const float qscale = 0.17677669529663689f;

    float acc[4][4][4];
#pragma unroll
    for (int a = 0; a < 4; a++)
#pragma unroll
        for (int b = 0; b < 4; b++)
#pragma unroll
            for (int c = 0; c < 4; c++) acc[a][b][c] = 0.f;

    int nch = K / GBK;
    gemm_issue(sb, A, B, bm0, bn0, K, 0, 0, tid);

    for (int c = 0; c < nch; c++) {
        if (c + 1 < nch) {
            gemm_issue(sb, A, B, bm0, bn0, K, (c + 1) * GBK, (c + 1) & 1, tid);
            asm volatile("cp.async.wait_group 1;" ::: "memory");
        } else {
            asm volatile("cp.async.wait_group 0;" ::: "memory");
        }
        __syncthreads();

        uint32_t stb = sb + (c & 1) * STAGE;
#pragma unroll
        for (int ks = 0; ks < 4; ks++) {
            uint32_t ah[4][4], bh[4][2];
#pragma unroll
            for (int mt = 0; mt < 4; mt++) {
                int row = wm * 64 + mt * 16 + (lane & 15);
                int kc  = ks * 2 + (lane >> 4);
                ldx4(ah[mt], stb + OFF_A + row * 128 + ((kc ^ (row & 7)) << 4));
            }
#pragma unroll
            for (int nt = 0; nt < 4; nt++) {
                int row = wn * 32 + nt * 8 + (lane & 7);
                int kc  = ks * 2 + ((lane >> 3) & 1);
                ldx2(bh[nt], stb + OFF_B + row * 128 + ((kc ^ (row & 7)) << 4));
            }
#pragma unroll
            for (int mt = 0; mt < 4; mt++)
#pragma unroll
                for (int nt = 0; nt < 4; nt++)
                    mma16816(acc[mt][nt], ah[mt], bh[nt]);
        }
        __syncthreads();
    }

#pragma unroll
    for (int mt = 0; mt < 4; mt++) {
        int r0 = bm0 + wm * 64 + mt * 16 + (lane >> 2);
#pragma unroll
        for (int half_ = 0; half_ < 2; half_++) {
            int r = r0 + half_ * 8;
            size_t ob;
            if (EPI == 1) {
                int t = r, wi = t / SQ, s = t - wi * SQ;
                int bb2 = wi >> 6, nw = wi & 63;
                int wy = nw >> 3, wx = nw & 7;
                int iy = s / WSZ, ix = s - iy * WSZ;
                int rr = wy * WSZ + iy + SHF; if (rr >= HH)  rr -= HH;
                int cc2 = wx * WSZ + ix + SHF; if (cc2 >= WWI) cc2 -= WWI;
                ob = ((size_t)((bb2 * HH + rr) * WWI + cc2)) * DIMC;
            } else {
                ob = (size_t)r * N;
            }
#pragma unroll
            for (int nt = 0; nt < 4; nt++) {
                int cc = bn0 + wn * 32 + nt * 8 + (lane & 3) * 2;
                float v0 = acc[mt][nt][half_ * 2 + 0] + bias[cc];
                float v1 = acc[mt][nt][half_ * 2 + 1] + bias[cc + 1];
                if (EPI == 0) {
                    if (cc < 512) { v0 *= qscale; v1 *= qscale; }
                    __half2 hv;
                    hv.x = __float2half_rn(v0);
                    hv.y = __float2half_rn(v1);
                    *(__half2*)(outH + (size_t)r * N + cc) = hv;
                } else if (EPI == 2) {
                    __half2 hv;
                    hv.x = __float2half_rn(gelu_f(v0));
                    hv.y = __float2half_rn(gelu_f(v1));
                    *(__half2*)(outH + (size_t)r * N + cc) = hv;
                } else {
                    float2 a = *(const float2*)(add + ob + cc);
                    v0 += a.x; v1 += a.y;
                    float2 o; o.x = v0; o.y = v1;
                    *(float2*)(outF + ob + cc) = o;
                }
            }
        }
    }
}

// ---------------- MMA attention: block = (window, 4 heads) ---------------
#define APITCH 272
#define ATEN   (64*APITCH)
#define ASMEM  (3*ATEN)

__global__ void __launch_bounds__(128, 3)
attn_kernel(const __half* __restrict__ qkv, const __half* __restrict__ btab,
            __half* __restrict__ out_h)
{
    extern __shared__ char asmem[];
    uint32_t sb = smem_u32(asmem);
    int tid = threadIdx.x, lane = tid & 31, wid = tid >> 5;
    int w = blockIdx.x >> 2, hg = blockIdx.x & 3;
    int head = hg * 4 + wid;

    for (int idx = tid; idx < 49 * 3 * 16; idx += 128) {
        int c = idx & 15;
        int t = (idx >> 4) % 3;
        int s = idx / 48;
        const __half* g = qkv + ((size_t)(w * SQ + s)) * 1536 + t * 512 + hg * 128 + c * 8;
        cpa16(sb + t * ATEN + s * APITCH + c * 16, g);
    }
    cp_commit();
    for (int idx = tid; idx < 15 * 3 * 16; idx += 128) {
        int c = idx & 15;
        int t = (idx >> 4) % 3;
        int s = 49 + idx / 48;
        uint32_t d = sb + t * ATEN + s * APITCH + c * 16;
        asm volatile("st.shared.v4.b32 [%0], {%1,%1,%1,%1};" :: "r"(d), "r"(0));
    }
    asm volatile("cp.async.wait_group 0;" ::: "memory");
    __syncthreads();

    int nw = w & 63;
    int wc = (((nw >> 3) == 7) ? 2 : 0) | (((nw & 7) == 7) ? 1 : 0);
    const __half* bt = btab + ((size_t)(wc * 16 + head)) * 4096;

    uint32_t qh = sb + 0 * ATEN + wid * 64;
    uint32_t kh = sb + 1 * ATEN + wid * 64;
    uint32_t vh = sb + 2 * ATEN + wid * 64;

    uint32_t bK[8][2][2];
#pragma unroll
    for (int p = 0; p < 4; p++)
#pragma unroll
        for (int ks = 0; ks < 2; ks++) {
            uint32_t t[4];
            ldx4(t, kh + (p * 16 + (lane & 15)) * APITCH + (ks * 2 + (lane >> 4)) * 16);
            bK[2*p  ][ks][0] = t[0]; bK[2*p  ][ks][1] = t[2];
            bK[2*p+1][ks][0] = t[1]; bK[2*p+1][ks][1] = t[3];
        }
    uint32_t bV[4][4][2];
#pragma unroll
    for (int dt = 0; dt < 4; dt++)
#pragma unroll
        for (int jp = 0; jp < 2; jp++) {
            uint32_t t[4];
            ldx4t(t, vh + (jp * 32 + (lane >> 3) * 8 + (lane & 7)) * APITCH + dt * 16);
            bV[dt][jp*2  ][0] = t[0]; bV[dt][jp*2  ][1] = t[1];
            bV[dt][jp*2+1][0] = t[2]; bV[dt][jp*2+1][1] = t[3];
        }

    int qr = lane >> 2;
    int qc = 2 * (lane & 3);

#pragma unroll
    for (int ms = 0; ms < 4; ms++) {
        uint32_t aQ[2][4];
        ldx4(aQ[0], qh + (ms * 16 + (lane & 15)) * APITCH + (0 + (lane >> 4)) * 16);
        ldx4(aQ[1], qh + (ms * 16 + (lane & 15)) * APITCH + (2 + (lane >> 4)) * 16);

        float S[8][4];
#pragma unroll
        for (int nt = 0; nt < 8; nt++) {
            S[nt][0] = S[nt][1] = S[nt][2] = S[nt][3] = 0.f;
            mma16816(S[nt], aQ[0], bK[nt][0]);
            mma16816(S[nt], aQ[1], bK[nt][1]);
        }

        int i1 = ms * 16 + qr, i2 = i1 + 8;
        const __half* bt1 = bt + i1 * 64 + qc;
        const __half* bt2 = bt + i2 * 64 + qc;
#pragma unroll
        for (int nt = 0; nt < 8; nt++) {
            float2 b1 = __half22float2(*(const __half2*)(bt1 + nt * 8));
            float2 b2 = __half22float2(*(const __half2*)(bt2 + nt * 8));
            S[nt][0] += b1.x; S[nt][1] += b1.y;
            S[nt][2] += b2.x; S[nt][3] += b2.y;
        }

        float mx1 = -1e30f, mx2 = -1e30f;
#pragma unroll
        for (int nt = 0; nt < 8; nt++) {
            mx1 = fmaxf(mx1, fmaxf(S[nt][0], S[nt][1]));
            mx2 = fmaxf(mx2, fmaxf(S[nt][2], S[nt][3]));
        }
        mx1 = fmaxf(mx1, __shfl_xor_sync(0xffffffffu, mx1, 1));
        mx1 = fmaxf(mx1, __shfl_xor_sync(0xffffffffu, mx1, 2));
        mx2 = fmaxf(mx2, __shfl_xor_sync(0xffffffffu, mx2, 1));
        mx2 = fmaxf(mx2, __shfl_xor_sync(0xffffffffu, mx2, 2));

        float sm1 = 0.f, sm2 = 0.f;
#pragma unroll
        for (int nt = 0; nt < 8; nt++) {
            S[nt][0] = __expf(S[nt][0] - mx1);
            S[nt][1] = __expf(S[nt][1] - mx1);
            S[nt][2] = __expf(S[nt][2] - mx2);
            S[nt][3] = __expf(S[nt][3] - mx2);
            sm1 += S[nt][0] + S[nt][1];
            sm2 += S[nt][2] + S[nt][3];
        }
        sm1 += __shfl_xor_sync(0xffffffffu, sm1, 1);
        sm1 += __shfl_xor_sync(0xffffffffu, sm1, 2);
        sm2 += __shfl_xor_sync(0xffffffffu, sm2, 1);
        sm2 += __shfl_xor_sync(0xffffffffu, sm2, 2);
        float r1 = 1.f / sm1, r2 = 1.f / sm2;

        float O[4][4];
#pragma unroll
        for (int dt = 0; dt < 4; dt++)
            O[dt][0] = O[dt][1] = O[dt][2] = O[dt][3] = 0.f;
#pragma unroll
        for (int kj = 0; kj < 4; kj++) {
            uint32_t aP[4];
            __half2 h;
            h = __floats2half2_rn(S[2*kj][0] * r1, S[2*kj][1] * r1);     aP[0] = *(uint32_t*)&h;
            h = __floats2half2_rn(S[2*kj][2] * r2, S[2*kj][3] * r2);     aP[1] = *(uint32_t*)&h;
            h = __floats2half2_rn(S[2*kj+1][0] * r1, S[2*kj+1][1] * r1); aP[2] = *(uint32_t*)&h;
            h = __floats2half2_rn(S[2*kj+1][2] * r2, S[2*kj+1][3] * r2); aP[3] = *(uint32_t*)&h;
#pragma unroll
            for (int dt = 0; dt < 4; dt++)
                mma16816(O[dt], aP, bV[dt][kj]);
        }

        if (i1 < SQ) {
            size_t ob = ((size_t)(w * SQ + i1)) * DIMC + head * HDIM + qc;
#pragma unroll
            for (int dt = 0; dt < 4; dt++) {
                __half2 hv = __floats2half2_rn(O[dt][0], O[dt][1]);
                *(__half2*)(out_h + ob + dt * 8) = hv;
            }
        }
        if (i2 < SQ) {
            size_t ob = ((size_t)(w * SQ + i2)) * DIMC + head * HDIM + qc;
#pragma unroll
            for (int dt = 0; dt < 4; dt++) {
                __half2 hv = __floats2half2_rn(O[dt][2], O[dt][3]);
                *(__half2*)(out_h + ob + dt * 8) = hv;
            }
        }
    }
}

// ---------------- launch --------------------------------------------------
extern "C" void kernel_launch(void* const* d_in, const int* in_sizes, int n_in,
                              void* d_out, int out_size)
{
    const float* x      = (const float*)d_in[0];
    const float* qkv_w  = (const float*)d_in[1];
    const float* qkv_b  = (const float*)d_in[2];
    const float* proj_w = (const float*)d_in[3];
    const float* proj_b = (const float*)d_in[4];
    const float* relb   = (const float*)d_in[5];
    const float* n1g    = (const float*)d_in[6];
    const float* n1b    = (const float*)d_in[7];
    const float* n2g    = (const float*)d_in[8];
    const float* n2b    = (const float*)d_in[9];
    const float* w1     = (const float*)d_in[10];
    const float* b1     = (const float*)d_in[11];
    const float* w2     = (const float*)d_in[12];
    const float* b2     = (const float*)d_in[13];
    float* out = (float*)d_out;

    __half *wt, *win, *qkvs, *att, *ln2s, *m1, *btab;
    float *x1;
    cudaGetSymbolAddress((void**)&wt,   g_wt);
    cudaGetSymbolAddress((void**)&win,  g_win);
    cudaGetSymbolAddress((void**)&qkvs, g_qkv);
    cudaGetSymbolAddress((void**)&att,  g_att);
    cudaGetSymbolAddress((void**)&x1,   g_x1);
    cudaGetSymbolAddress((void**)&ln2s, g_ln2);
    cudaGetSymbolAddress((void**)&m1,   g_m1);
    cudaGetSymbolAddress((void**)&btab, g_btab);

    cudaFuncSetAttribute(gemm_kernel<0>, cudaFuncAttributeMaxDynamicSharedMemorySize, GEMM_SMEM);
    cudaFuncSetAttribute(gemm_kernel<1>, cudaFuncAttributeMaxDynamicSharedMemorySize, GEMM_SMEM);
    cudaFuncSetAttribute(gemm_kernel<2>, cudaFuncAttributeMaxDynamicSharedMemorySize, GEMM_SMEM);
    cudaFuncSetAttribute(gemm_kernel<3>, cudaFuncAttributeMaxDynamicSharedMemorySize, GEMM_SMEM);
    cudaFuncSetAttribute(attn_kernel,    cudaFuncAttributeMaxDynamicSharedMemorySize, ASMEM);

    // fused prep: weight transpose + bias/mask table
    prep_kernel<<<(PREP_TOT + 255)/256, 256>>>(qkv_w, proj_w, w1, w2, relb, wt, btab);

    const int lnBlocks = (TOK * 32) / 256;

    // 1. LN1 + roll + window partition -> fp16
    ln_kernel<<<lnBlocks, 256>>>(x, n1g, n1b, win, 1);

    // 2. QKV GEMM [TOK,512]x[512,1536] -> fp16 (q pre-scaled)
    gemm_kernel<0><<<dim3(1536/GBN, TOK/GBM), 256, GEMM_SMEM>>>(
        win, wt + OW_QKV, qkv_b, nullptr, nullptr, qkvs, 1536, 512);

    // 3. MMA windowed attention -> fp16
    attn_kernel<<<WTOT * 4, 128, ASMEM>>>(qkvs, btab, att);

    // 4. proj GEMM + fused window-reverse/unshift/skip/bias -> x1 (fp32)
    gemm_kernel<1><<<dim3(512/GBN, TOK/GBM), 256, GEMM_SMEM>>>(
        att, wt + OW_PROJ, proj_b, x, x1, nullptr, 512, 512);

    // 5. LN2 -> fp16
    ln_kernel<<<lnBlocks, 256>>>(x1, n2g, n2b, ln2s, 0);

    // 6. MLP1 GEMM + bias + exact GELU -> fp16
    gemm_kernel<2><<<dim3(MLPD/GBN, TOK/GBM), 256, GEMM_SMEM>>>(
        ln2s, wt + OW_W1, b1, nullptr, nullptr, m1, MLPD, 512);

    // 7. MLP2 GEMM + bias + residual -> out (fp32)
    gemm_kernel<3><<<dim3(512/GBN, TOK/GBM), 256, GEMM_SMEM>>>(
        m1, wt + OW_W2, b2, x1, out, nullptr, 512, 2048);
}

// round 17
// speedup vs baseline: 1.0033x; 1.0033x over previous
#include <cuda_runtime.h>
#include <cuda_fp16.h>
#include <cstdint>
#include <math.h>

// ---------------- problem constants ----------------
#define BB     32
#define HH     56
#define WWI    56
#define DIMC   512
#define WSZ    7
#define SHF    3
#define NHEAD  16
#define HDIM   32
#define MLPD   2048
#define SQ     49
#define TOK    (BB*HH*WWI)   // 100352
#define WTOT   (BB*64)       // 2048

// weight-transpose offsets (elements) in the packed wT array
#define OW_QKV  0
#define OW_PROJ (512*1536)
#define OW_W1   (OW_PROJ + 512*512)
#define OW_W2   (OW_W1 + 512*2048)
#define WT_TOT  (OW_W2 + 2048*512)
#define BTAB_N  (4*16*64*64)
#define PREP_TOT (WT_TOT + BTAB_N)

// ---------------- scratch ----------------
__device__ __half g_wt  [WT_TOT];
__device__ __half g_win [(size_t)TOK*DIMC];
__device__ __half g_qkv [(size_t)TOK*3*DIMC];
__device__ __half g_att [(size_t)TOK*DIMC];
__device__ float  g_x1  [(size_t)TOK*DIMC];
__device__ __half g_ln2 [(size_t)TOK*DIMC];
__device__ __half g_m1  [(size_t)TOK*MLPD];
__device__ __half g_btab[BTAB_N];            // bias+mask table, 512 KB

__device__ __forceinline__ float gelu_f(float x) {
    return 0.5f * x * (1.0f + erff(x * 0.70710678118654752f));
}

// ---------------- PTX helpers ----------------
__device__ __forceinline__ uint32_t smem_u32(const void* p) {
    uint32_t a;
    asm("{ .reg .u64 t; cvta.to.shared.u64 t, %1; cvt.u32.u64 %0, t; }" : "=r"(a) : "l"(p));
    return a;
}
__device__ __forceinline__ void cpa16(uint32_t s, const void* g) {
    asm volatile("cp.async.cg.shared.global [%0], [%1], 16;" :: "r"(s), "l"(g));
}
__device__ __forceinline__ void cp_commit() {
    asm volatile("cp.async.commit_group;" ::: "memory");
}
__device__ __forceinline__ void ldx4(uint32_t* r, uint32_t a) {
    asm volatile("ldmatrix.sync.aligned.m8n8.x4.shared.b16 {%0,%1,%2,%3}, [%4];"
        : "=r"(r[0]), "=r"(r[1]), "=r"(r[2]), "=r"(r[3]) : "r"(a));
}
__device__ __forceinline__ void ldx4t(uint32_t* r, uint32_t a) {
    asm volatile("ldmatrix.sync.aligned.m8n8.x4.trans.shared.b16 {%0,%1,%2,%3}, [%4];"
        : "=r"(r[0]), "=r"(r[1]), "=r"(r[2]), "=r"(r[3]) : "r"(a));
}
__device__ __forceinline__ void ldx2(uint32_t* r, uint32_t a) {
    asm volatile("ldmatrix.sync.aligned.m8n8.x2.shared.b16 {%0,%1}, [%2];"
        : "=r"(r[0]), "=r"(r[1]) : "r"(a));
}
__device__ __forceinline__ void mma16816(float* d, const uint32_t* a, const uint32_t* b) {
    asm volatile("mma.sync.aligned.m16n8k16.row.col.f32.f16.f16.f32 "
        "{%0,%1,%2,%3}, {%4,%5,%6,%7}, {%8,%9}, {%0,%1,%2,%3};"
        : "+f"(d[0]), "+f"(d[1]), "+f"(d[2]), "+f"(d[3])
        : "r"(a[0]), "r"(a[1]), "r"(a[2]), "r"(a[3]), "r"(b[0]), "r"(b[1]));
}

// ---------------- fused prep: weight transpose + bias/mask table ---------
__global__ void prep_kernel(const float* __restrict__ Wqkv,
                            const float* __restrict__ Wproj,
                            const float* __restrict__ W1,
                            const float* __restrict__ W2,
                            const float* __restrict__ relb,
                            __half* __restrict__ T,
                            __half* __restrict__ BT)
{
    int i = blockIdx.x * 256 + threadIdx.x;
    if (i >= PREP_TOT) return;
    if (i < WT_TOT) {
        const float* W; int K, N, base;
        if (i < OW_PROJ)      { W = Wqkv;  K = 512;  N = 1536; base = OW_QKV; }
        else if (i < OW_W1)   { W = Wproj; K = 512;  N = 512;  base = OW_PROJ; }
        else if (i < OW_W2)   { W = W1;    K = 512;  N = 2048; base = OW_W1; }
        else                  { W = W2;    K = 2048; N = 512;  base = OW_W2; }
        int li = i - base;
        int n = li / K, k = li - n * K;
        T[i] = __float2half_rn(W[(size_t)k * N + n]);
    } else {
        int idx = i - WT_TOT;
        int j  = idx & 63;
        int ii = (idx >> 6) & 63;
        int h  = (idx >> 12) & 15;
        int wc = idx >> 16;
        float v;
        if (ii < SQ && j < SQ) {
            int yi = ii / 7, xi = ii - yi * 7;
            int yj = j / 7,  xj = j - yj * 7;
            v = relb[((yi - yj + 6) * 13 + (xi - xj + 6)) * NHEAD + h];
            int er = wc >> 1, ec = wc & 1;
            int mi = (er ? (yi < 4 ? 1 : 2) : 0) * 3 + (ec ? (xi < 4 ? 1 : 2) : 0);
            int mj = (er ? (yj < 4 ? 1 : 2) : 0) * 3 + (ec ? (xj < 4 ? 1 : 2) : 0);
            if (mi != mj) v -= 100.0f;
        } else {
            v = -20000.0f;
        }
        BT[idx] = __float2half_rn(v);
    }
}

// ---------------- LayerNorm (+ roll + window gather), fp16 out -----------
__global__ void ln_kernel(const float* __restrict__ src,
                          const float* __restrict__ gamma,
                          const float* __restrict__ beta,
                          __half* __restrict__ dst, int gather)
{
    int gw = (blockIdx.x * blockDim.x + threadIdx.x) >> 5;
    if (gw >= TOK) return;
    int lane = threadIdx.x & 31;

    int srow;
    if (gather) {
        int w  = gw / SQ, s = gw - w * SQ;
        int bb = w >> 6, nw = w & 63;
        int wy = nw >> 3, wx = nw & 7;
        int iy = s / WSZ, ix = s - iy * WSZ;
        int row = wy * WSZ + iy + SHF; if (row >= HH)  row -= HH;
        int col = wx * WSZ + ix + SHF; if (col >= WWI) col -= WWI;
        srow = (bb * HH + row) * WWI + col;
    } else {
        srow = gw;
    }

    const float4* sp = (const float4*)(src + (size_t)srow * DIMC);
    float4 v[4];
    float sum = 0.f, sq = 0.f;
#pragma unroll
    for (int i = 0; i < 4; i++) {
        v[i] = sp[lane + i * 32];
        sum += v[i].x + v[i].y + v[i].z + v[i].w;
        sq  += v[i].x*v[i].x + v[i].y*v[i].y + v[i].z*v[i].z + v[i].w*v[i].w;
    }
#pragma unroll
    for (int o = 16; o > 0; o >>= 1) {
        sum += __shfl_xor_sync(0xffffffffu, sum, o);
        sq  += __shfl_xor_sync(0xffffffffu, sq,  o);
    }
    float mean = sum * (1.0f / DIMC);
    float var  = sq  * (1.0f / DIMC) - mean * mean;
    float inv  = rsqrtf(var + 1e-5f);

    const float4* gp = (const float4*)gamma;
    const float4* bp = (const float4*)beta;
    size_t rb = (size_t)gw * DIMC;
#pragma unroll
    for (int i = 0; i < 4; i++) {
        float4 g = gp[lane + i * 32];
        float4 b = bp[lane + i * 32];
        __half2 h0, h1;
        h0.x = __float2half_rn((v[i].x - mean) * inv * g.x + b.x);
        h0.y = __float2half_rn((v[i].y - mean) * inv * g.y + b.y);
        h1.x = __float2half_rn((v[i].z - mean) * inv * g.z + b.z);
        h1.y = __float2half_rn((v[i].w - mean) * inv * g.w + b.w);
        int e = (lane + i * 32) * 4;
        uint2 pk;
        pk.x = *(uint32_t*)&h0;
        pk.y = *(uint32_t*)&h1;
        *(uint2*)(dst + rb + e) = pk;
    }
}

// ---------------- fp16 GEMM via mma.sync, 128x128x64, 2-stage (champion) -
// EPI 0: +bias, q-cols (cc<512) scaled -> fp16 outH      (QKV)
// EPI 1: +bias +add[map(row)] -> fp32 outF[map(row)]     (proj scatter)
// EPI 2: gelu(+bias) -> fp16 outH                        (MLP1)
// EPI 3: +bias +add[row*N] -> fp32 outF[row*N]           (MLP2)
#define GBM 128
#define GBN 128
#define GBK 64
#define STAGE  (32*1024)
#define OFF_A  0
#define OFF_B  16384
#define GEMM_SMEM (2*STAGE)

__device__ __forceinline__ void gemm_issue(
    uint32_t sb, const __half* A, const __half* B,
    int bm0, int bn0, int K, int k0, int stage, int tid)
{
    uint32_t stb = sb + stage * STAGE;
#pragma unroll
    for (int i = 0; i < 4; i++) {
        int idx = i * 256 + tid;
        int row = idx >> 3, cch = idx & 7;
        uint32_t soff = row * 128 + ((cch ^ (row & 7)) << 4);
        cpa16(stb + OFF_A + soff, A + (size_t)(bm0 + row) * K + k0 + cch * 8);
        cpa16(stb + OFF_B + soff, B + (size_t)(bn0 + row) * K + k0 + cch * 8);
    }
    cp_commit();
}

template<int EPI>
__global__ void __launch_bounds__(256, 2)
gemm_kernel(const __half* __restrict__ A, const __half* __restrict__ B,
            const float* __restrict__ bias, const float* __restrict__ add,
            float* __restrict__ outF, __half* __restrict__ outH,
            int N, int K)
{
    extern __shared__ char smc[];
    uint32_t sb = smem_u32(smc);
    int tid  = threadIdx.x;
    int lane = tid & 31;
    int warp = tid >> 5;
    int wm = warp & 1, wn = warp >> 1;
    int bm0 = blockIdx.y * GBM;
    int bn0 = blockIdx.x * GBN;
    const float qscale = 0.17677669529663689f;

    float acc[4][4][4];
#pragma unroll
    for (int a = 0; a < 4; a++)
#pragma unroll
        for (int b = 0; b < 4; b++)
#pragma unroll
            for (int c = 0; c < 4; c++) acc[a][b][c] = 0.f;

    int nch = K / GBK;
    gemm_issue(sb, A, B, bm0, bn0, K, 0, 0, tid);

    for (int c = 0; c < nch; c++) {
        if (c + 1 < nch) {
            gemm_issue(sb, A, B, bm0, bn0, K, (c + 1) * GBK, (c + 1) & 1, tid);
            asm volatile("cp.async.wait_group 1;" ::: "memory");
        } else {
            asm volatile("cp.async.wait_group 0;" ::: "memory");
        }
        __syncthreads();

        uint32_t stb = sb + (c & 1) * STAGE;
#pragma unroll
        for (int ks = 0; ks < 4; ks++) {
            uint32_t ah[4][4], bh[4][2];
#pragma unroll
            for (int mt = 0; mt < 4; mt++) {
                int row = wm * 64 + mt * 16 + (lane & 15);
                int kc  = ks * 2 + (lane >> 4);
                ldx4(ah[mt], stb + OFF_A + row * 128 + ((kc ^ (row & 7)) << 4));
            }
#pragma unroll
            for (int nt = 0; nt < 4; nt++) {
                int row = wn * 32 + nt * 8 + (lane & 7);
                int kc  = ks * 2 + ((lane >> 3) & 1);
                ldx2(bh[nt], stb + OFF_B + row * 128 + ((kc ^ (row & 7)) << 4));
            }
#pragma unroll
            for (int mt = 0; mt < 4; mt++)
#pragma unroll
                for (int nt = 0; nt < 4; nt++)
                    mma16816(acc[mt][nt], ah[mt], bh[nt]);
        }
        __syncthreads();
    }

#pragma unroll
    for (int mt = 0; mt < 4; mt++) {
        int r0 = bm0 + wm * 64 + mt * 16 + (lane >> 2);
#pragma unroll
        for (int half_ = 0; half_ < 2; half_++) {
            int r = r0 + half_ * 8;
            size_t ob;
            if (EPI == 1) {
                int t = r, wi = t / SQ, s = t - wi * SQ;
                int bb2 = wi >> 6, nw = wi & 63;
                int wy = nw >> 3, wx = nw & 7;
                int iy = s / WSZ, ix = s - iy * WSZ;
                int rr = wy * WSZ + iy + SHF; if (rr >= HH)  rr -= HH;
                int cc2 = wx * WSZ + ix + SHF; if (cc2 >= WWI) cc2 -= WWI;
                ob = ((size_t)((bb2 * HH + rr) * WWI + cc2)) * DIMC;
            } else {
                ob = (size_t)r * N;
            }
#pragma unroll
            for (int nt = 0; nt < 4; nt++) {
                int cc = bn0 + wn * 32 + nt * 8 + (lane & 3) * 2;
                float v0 = acc[mt][nt][half_ * 2 + 0] + bias[cc];
                float v1 = acc[mt][nt][half_ * 2 + 1] + bias[cc + 1];
                if (EPI == 0) {
                    if (cc < 512) { v0 *= qscale; v1 *= qscale; }
                    __half2 hv;
                    hv.x = __float2half_rn(v0);
                    hv.y = __float2half_rn(v1);
                    *(__half2*)(outH + (size_t)r * N + cc) = hv;
                } else if (EPI == 2) {
                    __half2 hv;
                    hv.x = __float2half_rn(gelu_f(v0));
                    hv.y = __float2half_rn(gelu_f(v1));
                    *(__half2*)(outH + (size_t)r * N + cc) = hv;
                } else {
                    float2 a = *(const float2*)(add + ob + cc);
                    v0 += a.x; v1 += a.y;
                    float2 o; o.x = v0; o.y = v1;
                    *(float2*)(outF + ob + cc) = o;
                }
            }
        }
    }
}

// ---------------- MMA attention: block = (window, 4 heads) ---------------
#define APITCH 272
#define ATEN   (64*APITCH)
#define ASMEM  (3*ATEN)

__global__ void __launch_bounds__(128, 3)
attn_kernel(const __half* __restrict__ qkv, const __half* __restrict__ btab,
            __half* __restrict__ out_h)
{
    extern __shared__ char asmem[];
    uint32_t sb = smem_u32(asmem);
    int tid = threadIdx.x, lane = tid & 31, wid = tid >> 5;
    int w = blockIdx.x >> 2, hg = blockIdx.x & 3;
    int head = hg * 4 + wid;

    // fill: strength-reduced, purely additive addressing.
    // c = 16B chunk (0..15), sub = row phase (0..7).
    {
        int c = tid & 15;
        int sub = tid >> 4;
        const __half* gbase = qkv + (size_t)(w * SQ + sub) * 1536 + hg * 128 + c * 8;
        uint32_t sbase = sb + sub * APITCH + c * 16;
#pragma unroll
        for (int t = 0; t < 3; t++) {
            const __half* g = gbase + t * 512;
            uint32_t d = sbase + t * ATEN;
            for (int s = sub; s < SQ; s += 8) {
                cpa16(d, g);
                g += 8 * 1536;
                d += 8 * APITCH;
            }
        }
        cp_commit();
        // zero pad rows 49..63
        uint32_t dz = sb + (49 + sub) * APITCH + c * 16;
#pragma unroll
        for (int t = 0; t < 3; t++) {
            uint32_t d = dz + t * ATEN;
            for (int s = 49 + sub; s < 64; s += 8) {
                asm volatile("st.shared.v4.b32 [%0], {%1,%1,%1,%1};" :: "r"(d), "r"(0));
                d += 8 * APITCH;
            }
        }
    }
    asm volatile("cp.async.wait_group 0;" ::: "memory");
    __syncthreads();

    int nw = w & 63;
    int wc = (((nw >> 3) == 7) ? 2 : 0) | (((nw & 7) == 7) ? 1 : 0);
    const __half* bt = btab + ((size_t)(wc * 16 + head)) * 4096;

    uint32_t qh = sb + 0 * ATEN + wid * 64;
    uint32_t kh = sb + 1 * ATEN + wid * 64;
    uint32_t vh = sb + 2 * ATEN + wid * 64;

    uint32_t bK[8][2][2];
#pragma unroll
    for (int p = 0; p < 4; p++)
#pragma unroll
        for (int ks = 0; ks < 2; ks++) {
            uint32_t t[4];
            ldx4(t, kh + (p * 16 + (lane & 15)) * APITCH + (ks * 2 + (lane >> 4)) * 16);
            bK[2*p  ][ks][0] = t[0]; bK[2*p  ][ks][1] = t[2];
            bK[2*p+1][ks][0] = t[1]; bK[2*p+1][ks][1] = t[3];
        }
    uint32_t bV[4][4][2];
#pragma unroll
    for (int dt = 0; dt < 4; dt++)
#pragma unroll
        for (int jp = 0; jp < 2; jp++) {
            uint32_t t[4];
            ldx4t(t, vh + (jp * 32 + (lane >> 3) * 8 + (lane & 7)) * APITCH + dt * 16);
            bV[dt][jp*2  ][0] = t[0]; bV[dt][jp*2  ][1] = t[1];
            bV[dt][jp*2+1][0] = t[2]; bV[dt][jp*2+1][1] = t[3];
        }

    int qr = lane >> 2;
    int qc = 2 * (lane & 3);

#pragma unroll
    for (int ms = 0; ms < 4; ms++) {
        uint32_t aQ[2][4];
        ldx4(aQ[0], qh + (ms * 16 + (lane & 15)) * APITCH + (0 + (lane >> 4)) * 16);
        ldx4(aQ[1], qh + (ms * 16 + (lane & 15)) * APITCH + (2 + (lane >> 4)) * 16);

        float S[8][4];
#pragma unroll
        for (int nt = 0; nt < 8; nt++) {
            S[nt][0] = S[nt][1] = S[nt][2] = S[nt][3] = 0.f;
            mma16816(S[nt], aQ[0], bK[nt][0]);
            mma16816(S[nt], aQ[1], bK[nt][1]);
        }

        int i1 = ms * 16 + qr, i2 = i1 + 8;
        const __half* bt1 = bt + i1 * 64 + qc;
        const __half* bt2 = bt + i2 * 64 + qc;
#pragma unroll
        for (int nt = 0; nt < 8; nt++) {
            float2 b1 = __half22float2(*(const __half2*)(bt1 + nt * 8));
            float2 b2 = __half22float2(*(const __half2*)(bt2 + nt * 8));
            S[nt][0] += b1.x; S[nt][1] += b1.y;
            S[nt][2] += b2.x; S[nt][3] += b2.y;
        }

        float mx1 = -1e30f, mx2 = -1e30f;
#pragma unroll
        for (int nt = 0; nt < 8; nt++) {
            mx1 = fmaxf(mx1, fmaxf(S[nt][0], S[nt][1]));
            mx2 = fmaxf(mx2, fmaxf(S[nt][2], S[nt][3]));
        }
        mx1 = fmaxf(mx1, __shfl_xor_sync(0xffffffffu, mx1, 1));
        mx1 = fmaxf(mx1, __shfl_xor_sync(0xffffffffu, mx1, 2));
        mx2 = fmaxf(mx2, __shfl_xor_sync(0xffffffffu, mx2, 1));
        mx2 = fmaxf(mx2, __shfl_xor_sync(0xffffffffu, mx2, 2));

        float sm1 = 0.f, sm2 = 0.f;
#pragma unroll
        for (int nt = 0; nt < 8; nt++) {
            S[nt][0] = __expf(S[nt][0] - mx1);
            S[nt][1] = __expf(S[nt][1] - mx1);
            S[nt][2] = __expf(S[nt][2] - mx2);
            S[nt][3] = __expf(S[nt][3] - mx2);
            sm1 += S[nt][0] + S[nt][1];
            sm2 += S[nt][2] + S[nt][3];
        }
        sm1 += __shfl_xor_sync(0xffffffffu, sm1, 1);
        sm1 += __shfl_xor_sync(0xffffffffu, sm1, 2);
        sm2 += __shfl_xor_sync(0xffffffffu, sm2, 1);
        sm2 += __shfl_xor_sync(0xffffffffu, sm2, 2);
        float r1 = 1.f / sm1, r2 = 1.f / sm2;

        float O[4][4];
#pragma unroll
        for (int dt = 0; dt < 4; dt++)
            O[dt][0] = O[dt][1] = O[dt][2] = O[dt][3] = 0.f;
#pragma unroll
        for (int kj = 0; kj < 4; kj++) {
            uint32_t aP[4];
            __half2 h;
            h = __floats2half2_rn(S[2*kj][0] * r1, S[2*kj][1] * r1);     aP[0] = *(uint32_t*)&h;
            h = __floats2half2_rn(S[2*kj][2] * r2, S[2*kj][3] * r2);     aP[1] = *(uint32_t*)&h;
            h = __floats2half2_rn(S[2*kj+1][0] * r1, S[2*kj+1][1] * r1); aP[2] = *(uint32_t*)&h;
            h = __floats2half2_rn(S[2*kj+1][2] * r2, S[2*kj+1][3] * r2); aP[3] = *(uint32_t*)&h;
#pragma unroll
            for (int dt = 0; dt < 4; dt++)
                mma16816(O[dt], aP, bV[dt][kj]);
        }

        if (i1 < SQ) {
            size_t ob = ((size_t)(w * SQ + i1)) * DIMC + head * HDIM + qc;
#pragma unroll
            for (int dt = 0; dt < 4; dt++) {
                __half2 hv = __floats2half2_rn(O[dt][0], O[dt][1]);
                *(__half2*)(out_h + ob + dt * 8) = hv;
            }
        }
        if (i2 < SQ) {
            size_t ob = ((size_t)(w * SQ + i2)) * DIMC + head * HDIM + qc;
#pragma unroll
            for (int dt = 0; dt < 4; dt++) {
                __half2 hv = __floats2half2_rn(O[dt][2], O[dt][3]);
                *(__half2*)(out_h + ob + dt * 8) = hv;
            }
        }
    }
}

// ---------------- launch --------------------------------------------------
extern "C" void kernel_launch(void* const* d_in, const int* in_sizes, int n_in,
                              void* d_out, int out_size)
{
    const float* x      = (const float*)d_in[0];
    const float* qkv_w  = (const float*)d_in[1];
    const float* qkv_b  = (const float*)d_in[2];
    const float* proj_w = (const float*)d_in[3];
    const float* proj_b = (const float*)d_in[4];
    const float* relb   = (const float*)d_in[5];
    const float* n1g    = (const float*)d_in[6];
    const float* n1b    = (const float*)d_in[7];
    const float* n2g    = (const float*)d_in[8];
    const float* n2b    = (const float*)d_in[9];
    const float* w1     = (const float*)d_in[10];
    const float* b1     = (const float*)d_in[11];
    const float* w2     = (const float*)d_in[12];
    const float* b2     = (const float*)d_in[13];
    float* out = (float*)d_out;

    __half *wt, *win, *qkvs, *att, *ln2s, *m1, *btab;
    float *x1;
    cudaGetSymbolAddress((void**)&wt,   g_wt);
    cudaGetSymbolAddress((void**)&win,  g_win);
    cudaGetSymbolAddress((void**)&qkvs, g_qkv);
    cudaGetSymbolAddress((void**)&att,  g_att);
    cudaGetSymbolAddress((void**)&x1,   g_x1);
    cudaGetSymbolAddress((void**)&ln2s, g_ln2);
    cudaGetSymbolAddress((void**)&m1,   g_m1);
    cudaGetSymbolAddress((void**)&btab, g_btab);

    cudaFuncSetAttribute(gemm_kernel<0>, cudaFuncAttributeMaxDynamicSharedMemorySize, GEMM_SMEM);
    cudaFuncSetAttribute(gemm_kernel<1>, cudaFuncAttributeMaxDynamicSharedMemorySize, GEMM_SMEM);
    cudaFuncSetAttribute(gemm_kernel<2>, cudaFuncAttributeMaxDynamicSharedMemorySize, GEMM_SMEM);
    cudaFuncSetAttribute(gemm_kernel<3>, cudaFuncAttributeMaxDynamicSharedMemorySize, GEMM_SMEM);
    cudaFuncSetAttribute(attn_kernel,    cudaFuncAttributeMaxDynamicSharedMemorySize, ASMEM);

    // fused prep: weight transpose + bias/mask table
    prep_kernel<<<(PREP_TOT + 255)/256, 256>>>(qkv_w, proj_w, w1, w2, relb, wt, btab);

    const int lnBlocks = (TOK * 32) / 256;

    // 1. LN1 + roll + window partition -> fp16
    ln_kernel<<<lnBlocks, 256>>>(x, n1g, n1b, win, 1);

    // 2. QKV GEMM [TOK,512]x[512,1536] -> fp16 (q pre-scaled)
    gemm_kernel<0><<<dim3(1536/GBN, TOK/GBM), 256, GEMM_SMEM>>>(
        win, wt + OW_QKV, qkv_b, nullptr, nullptr, qkvs, 1536, 512);

    // 3. MMA windowed attention -> fp16
    attn_kernel<<<WTOT * 4, 128, ASMEM>>>(qkvs, btab, att);

    // 4. proj GEMM + fused window-reverse/unshift/skip/bias -> x1 (fp32)
    gemm_kernel<1><<<dim3(512/GBN, TOK/GBM), 256, GEMM_SMEM>>>(
        att, wt + OW_PROJ, proj_b, x, x1, nullptr, 512, 512);

    // 5. LN2 -> fp16
    ln_kernel<<<lnBlocks, 256>>>(x1, n2g, n2b, ln2s, 0);

    // 6. MLP1 GEMM + bias + exact GELU -> fp16
    gemm_kernel<2><<<dim3(MLPD/GBN, TOK/GBM), 256, GEMM_SMEM>>>(
        ln2s, wt + OW_W1, b1, nullptr, nullptr, m1, MLPD, 512);

    // 7. MLP2 GEMM + bias + residual -> out (fp32)
    gemm_kernel<3><<<dim3(512/GBN, TOK/GBM), 256, GEMM_SMEM>>>(
        m1, wt + OW_W2, b2, x1, out, nullptr, 512, 2048);
}